// round 8
// baseline (speedup 1.0000x reference)
#include <cuda_runtime.h>
#include <cuda_bf16.h>
#include <cstdint>

// Shapes (fixed)
#define NB 4
#define NQ 512
#define NK 512
#define ND 256
#define NH 256

#define STRIDE 260   // smem row stride (floats); conflict-free LDS.128 phases
#define TK 16        // keys per tile (double-buffered)

__device__ float g_qh[NB * NQ * NH];
__device__ float g_kh[NB * NK * NH];

__device__ __forceinline__ float tanh_ap(float x) {
    float y;
    asm("tanh.approx.f32 %0, %1;" : "=f"(y) : "f"(x));
    return y;
}

__device__ __forceinline__ void cp16(unsigned dst, const float* src) {
    asm volatile("cp.async.cg.shared.global [%0], [%1], 16;" :: "r"(dst), "l"(src));
}
__device__ __forceinline__ void cp_commit() {
    asm volatile("cp.async.commit_group;");
}

// ---------------------------------------------------------------------------
// Projection GEMM: C[2048x256] = A[2048x256] @ W[256x256]
// ---------------------------------------------------------------------------
__global__ __launch_bounds__(256) void proj_kernel(
    const float* __restrict__ Aq, const float* __restrict__ Wq,
    const float* __restrict__ Ak, const float* __restrict__ Wk)
{
    const float* A; const float* W; float* C;
    if (blockIdx.z == 0) { A = Aq; W = Wq; C = g_qh; }
    else                 { A = Ak; W = Wk; C = g_kh; }

    __shared__ float As[16][68];
    __shared__ float Bs[16][68];

    const int t    = threadIdx.x;
    const int row0 = blockIdx.y * 64;
    const int col0 = blockIdx.x * 64;
    const int ty   = t >> 4;
    const int tx   = t & 15;

    float acc[4][4] = {};

    for (int k0 = 0; k0 < ND; k0 += 16) {
        {
            int r  = t >> 2;
            int c4 = (t & 3) * 4;
            float4 v = *(const float4*)&A[(row0 + r) * ND + k0 + c4];
            As[c4 + 0][r] = v.x;
            As[c4 + 1][r] = v.y;
            As[c4 + 2][r] = v.z;
            As[c4 + 3][r] = v.w;
        }
        {
            int r  = t >> 4;
            int c4 = (t & 15) * 4;
            *(float4*)&Bs[r][c4] = *(const float4*)&W[(k0 + r) * NH + col0 + c4];
        }
        __syncthreads();
        #pragma unroll
        for (int kk = 0; kk < 16; kk++) {
            float4 av = *(float4*)&As[kk][ty * 4];
            float4 bv = *(float4*)&Bs[kk][tx * 4];
            float a_[4] = {av.x, av.y, av.z, av.w};
            float b_[4] = {bv.x, bv.y, bv.z, bv.w};
            #pragma unroll
            for (int i = 0; i < 4; i++)
                #pragma unroll
                for (int j = 0; j < 4; j++)
                    acc[i][j] += a_[i] * b_[j];
        }
        __syncthreads();
    }

    #pragma unroll
    for (int i = 0; i < 4; i++) {
        float4 v = make_float4(acc[i][0], acc[i][1], acc[i][2], acc[i][3]);
        *(float4*)&C[(row0 + ty * 4 + i) * NH + col0 + tx * 4] = v;
    }
}

// ---------------------------------------------------------------------------
// Fused attention: cp.async double-buffered 16-key tiles, MUFU-fed pipeline.
// 512 blocks x 256 threads; warp (q = w>>1, s = w&1); b = blockIdx & 3.
// Phase A lane map: key = s*8 + (lane&7), h-quarter = (lane>>3)*64;
//   per-key sum via shfl_xor(8) + shfl_xor(16).
// Phase C lane map: d-offset = s*128 + lane*4.
// ---------------------------------------------------------------------------
__global__ __launch_bounds__(256, 4) void attn_kernel(
    const float* __restrict__ values,
    const float* __restrict__ wv,
    const int*   __restrict__ valid_lens,
    float*       __restrict__ out)
{
    __shared__ float sbuf[2 * TK * STRIDE];   // 33280 B: double-buffered tiles
    __shared__ float attn_s[4 * NK];          // 8192 B
    __shared__ float s_qh[4 * NH];            // 4096 B
    __shared__ float s_wv[NH];                // 1024 B
    __shared__ float s_inv[4];

    const int t    = threadIdx.x;
    const int w    = t >> 5;
    const int lane = t & 31;
    const int q    = w >> 1;
    const int s    = w & 1;
    const int b    = blockIdx.x & 3;
    const int qblk = blockIdx.x >> 2;
    const int vl   = valid_lens[b];           // uniform across block

    const unsigned sbuf_u32 = (unsigned)__cvta_generic_to_shared(sbuf);

    // ---------------- prologue: stage qh + wv ----------------
    {
        int r = t >> 6;
        int c = (t & 63) * 4;
        *(float4*)&s_qh[r * NH + c] =
            *(const float4*)&g_qh[(b * NQ + qblk * 4 + r) * NH + c];
    }
    if (t < 64) *(float4*)&s_wv[t * 4] = *(const float4*)&wv[t * 4];

    // ---------------- Phase A: scores -> attn_s ----------------
    const float* khb  = &g_kh[(b * NK) * NH];
    const int   key   = s * 8 + (lane & 7);   // key-in-tile this lane scores
    const int   h0    = (lane >> 3) * 64;     // h-quarter this lane covers
    const float* myq  = &s_qh[q * NH + h0];
    const float* mwv  = &s_wv[h0];
    const int nTA = (vl + TK - 1) >> 4;

    // prefetch tile 0
    {
        const float* src = khb;
        unsigned dbase = sbuf_u32;
        #pragma unroll
        for (int r = 0; r < 4; ++r) {
            int i  = t + 256 * r;             // 0..1023
            int k  = i >> 6;
            int h4 = (i & 63) * 4;
            cp16(dbase + (unsigned)(k * STRIDE + h4) * 4u, src + k * NH + h4);
        }
        cp_commit();
    }
    __syncthreads();                           // qh/wv staged (also before 1st compute)

    for (int tile = 0; tile < nTA; ++tile) {
        if (tile + 1 < nTA) {                  // prefetch next into other buffer
            const float* src = &khb[(tile + 1) * TK * NH];
            unsigned dbase = sbuf_u32 + (unsigned)(((tile + 1) & 1) * TK * STRIDE) * 4u;
            #pragma unroll
            for (int r = 0; r < 4; ++r) {
                int i  = t + 256 * r;
                int k  = i >> 6;
                int h4 = (i & 63) * 4;
                cp16(dbase + (unsigned)(k * STRIDE + h4) * 4u, src + k * NH + h4);
            }
            cp_commit();
            asm volatile("cp.async.wait_group 1;");
        } else {
            asm volatile("cp.async.wait_group 0;");
        }
        __syncthreads();                       // tile data visible to all warps

        const float* kb = &sbuf[(tile & 1) * TK * STRIDE + key * STRIDE + h0];
        float a0 = 0.f, a1 = 0.f;
        #pragma unroll
        for (int h = 0; h < 64; h += 8) {
            float4 k0  = *(const float4*)&kb[h];
            float4 q0  = *(const float4*)&myq[h];
            float4 w0  = *(const float4*)&mwv[h];
            float4 k1  = *(const float4*)&kb[h + 4];
            float4 q1  = *(const float4*)&myq[h + 4];
            float4 w1  = *(const float4*)&mwv[h + 4];
            a0 += w0.x * tanh_ap(q0.x + k0.x);
            a1 += w1.x * tanh_ap(q1.x + k1.x);
            a0 += w0.y * tanh_ap(q0.y + k0.y);
            a1 += w1.y * tanh_ap(q1.y + k1.y);
            a0 += w0.z * tanh_ap(q0.z + k0.z);
            a1 += w1.z * tanh_ap(q1.z + k1.z);
            a0 += w0.w * tanh_ap(q0.w + k0.w);
            a1 += w1.w * tanh_ap(q1.w + k1.w);
        }
        float acc = a0 + a1;
        acc += __shfl_xor_sync(0xffffffffu, acc, 8);   // combine h-quarters
        acc += __shfl_xor_sync(0xffffffffu, acc, 16);
        if (lane < 8)
            attn_s[q * NK + tile * TK + key] = acc;
        __syncthreads();                       // reads done before buffer reuse
    }

    // ---------------- Phase C prefetch tile 0 (overlap with softmax) ----------
    const int nTC = (vl + TK - 1) >> 4;
    const float* vb = &values[(b * NK) * ND];
    {
        unsigned dbase = sbuf_u32;
        #pragma unroll
        for (int r = 0; r < 4; ++r) {
            int i  = t + 256 * r;
            int k  = i >> 6;
            int h4 = (i & 63) * 4;
            cp16(dbase + (unsigned)(k * STRIDE + h4) * 4u, vb + k * ND + h4);
        }
        cp_commit();
    }

    // ---------------- Phase B: masked softmax (even warps) ----------------
    if (s == 0) {
        float mx = -1.0e30f;
        for (int i = 0; i < 16; i++) {
            int k = i * 32 + lane;
            float v = (k < vl) ? attn_s[q * NK + k] : -1.0e6f;
            mx = fmaxf(mx, v);
        }
        #pragma unroll
        for (int o = 16; o > 0; o >>= 1)
            mx = fmaxf(mx, __shfl_xor_sync(0xffffffffu, mx, o));

        float sum = 0.f;
        for (int i = 0; i < 16; i++) {
            int k = i * 32 + lane;
            float v = (k < vl) ? attn_s[q * NK + k] : -1.0e6f;
            float e = __expf(v - mx);          // masked -> exact 0
            sum += e;
            attn_s[q * NK + k] = e;
        }
        #pragma unroll
        for (int o = 16; o > 0; o >>= 1)
            sum += __shfl_xor_sync(0xffffffffu, sum, o);
        if (lane == 0) s_inv[q] = 1.0f / sum;
    }

    // ---------------- Phase C: out = attn @ values ----------------
    float4 o0 = make_float4(0.f, 0.f, 0.f, 0.f);
    const int dOff = s * 128 + lane * 4;

    for (int tile = 0; tile < nTC; ++tile) {
        if (tile + 1 < nTC) {
            const float* src = &vb[(tile + 1) * TK * ND];
            unsigned dbase = sbuf_u32 + (unsigned)(((tile + 1) & 1) * TK * STRIDE) * 4u;
            #pragma unroll
            for (int r = 0; r < 4; ++r) {
                int i  = t + 256 * r;
                int k  = i >> 6;
                int h4 = (i & 63) * 4;
                cp16(dbase + (unsigned)(k * STRIDE + h4) * 4u, src + k * ND + h4);
            }
            cp_commit();
            asm volatile("cp.async.wait_group 1;");
        } else {
            asm volatile("cp.async.wait_group 0;");
        }
        __syncthreads();                       // tile data + attn_s (tile 0) visible

        const float* vbuf = &sbuf[(tile & 1) * TK * STRIDE];
        #pragma unroll
        for (int kk = 0; kk < 16; ++kk) {
            float a = attn_s[q * NK + tile * TK + kk];   // broadcast
            float4 v0 = *(const float4*)&vbuf[kk * STRIDE + dOff];
            o0.x += a * v0.x; o0.y += a * v0.y;
            o0.z += a * v0.z; o0.w += a * v0.w;
        }
        __syncthreads();                       // reads done before buffer reuse
    }

    const float inv = s_inv[q];
    o0.x *= inv; o0.y *= inv; o0.z *= inv; o0.w *= inv;
    const int qrow = b * NQ + qblk * 4 + q;
    *(float4*)&out[qrow * ND + dOff] = o0;
}

// ---------------------------------------------------------------------------
extern "C" void kernel_launch(void* const* d_in, const int* in_sizes, int n_in,
                              void* d_out, int out_size)
{
    const float* queries = (const float*)d_in[0];
    const float* keys    = (const float*)d_in[1];
    const float* values  = (const float*)d_in[2];
    const float* Wq      = (const float*)d_in[3];
    const float* Wk      = (const float*)d_in[4];
    const float* wv      = (const float*)d_in[5];
    const int*   vlen    = (const int*)d_in[6];
    float* out = (float*)d_out;

    (void)in_sizes; (void)n_in; (void)out_size;

    dim3 pgrid(NH / 64, (NB * NQ) / 64, 2);
    proj_kernel<<<pgrid, 256>>>(queries, Wq, keys, Wk);

    attn_kernel<<<(NB * NQ) / 4, 256>>>(values, wv, vlen, out);
}

// round 9
// speedup vs baseline: 1.2613x; 1.2613x over previous
#include <cuda_runtime.h>
#include <cuda_bf16.h>
#include <cstdint>

// Shapes (fixed)
#define NB 4
#define NQ 512
#define NK 512
#define ND 256
#define NH 256

#define STRIDE 260   // smem row stride (floats); lane*260 % 32 banks = lane*4 -> conflict-free LDS.128
#define TK 32        // keys per tile (double-buffered)

// smem layout (floats) within dynamic buffer
#define OFF_KBUF 0
#define OFF_ATTN (2 * TK * STRIDE)              // 16640
#define OFF_QH   (OFF_ATTN + 8 * NK)            // 16640 + 4096 = 20736
#define OFF_WV   (OFF_QH + 8 * NH)              // 20736 + 2048 = 22784
#define SMEM_FLOATS (OFF_WV + NH)               // 23040
#define SMEM_BYTES (SMEM_FLOATS * 4)            // 92160

__device__ float g_qh[NB * NQ * NH];
__device__ float g_kh[NB * NK * NH];

__device__ __forceinline__ float tanh_ap(float x) {
    float y;
    asm("tanh.approx.f32 %0, %1;" : "=f"(y) : "f"(x));
    return y;
}

__device__ __forceinline__ void cp16(unsigned dst, const float* src) {
    asm volatile("cp.async.cg.shared.global [%0], [%1], 16;" :: "r"(dst), "l"(src));
}
__device__ __forceinline__ void cp_commit() {
    asm volatile("cp.async.commit_group;");
}

// ---------------------------------------------------------------------------
// Projection GEMM: C[2048x256] = A[2048x256] @ W[256x256]  (unchanged)
// ---------------------------------------------------------------------------
__global__ __launch_bounds__(256) void proj_kernel(
    const float* __restrict__ Aq, const float* __restrict__ Wq,
    const float* __restrict__ Ak, const float* __restrict__ Wk)
{
    const float* A; const float* W; float* C;
    if (blockIdx.z == 0) { A = Aq; W = Wq; C = g_qh; }
    else                 { A = Ak; W = Wk; C = g_kh; }

    __shared__ float As[16][68];
    __shared__ float Bs[16][68];

    const int t    = threadIdx.x;
    const int row0 = blockIdx.y * 64;
    const int col0 = blockIdx.x * 64;
    const int ty   = t >> 4;
    const int tx   = t & 15;

    float acc[4][4] = {};

    for (int k0 = 0; k0 < ND; k0 += 16) {
        {
            int r  = t >> 2;
            int c4 = (t & 3) * 4;
            float4 v = *(const float4*)&A[(row0 + r) * ND + k0 + c4];
            As[c4 + 0][r] = v.x;
            As[c4 + 1][r] = v.y;
            As[c4 + 2][r] = v.z;
            As[c4 + 3][r] = v.w;
        }
        {
            int r  = t >> 4;
            int c4 = (t & 15) * 4;
            *(float4*)&Bs[r][c4] = *(const float4*)&W[(k0 + r) * NH + col0 + c4];
        }
        __syncthreads();
        #pragma unroll
        for (int kk = 0; kk < 16; kk++) {
            float4 av = *(float4*)&As[kk][ty * 4];
            float4 bv = *(float4*)&Bs[kk][tx * 4];
            float a_[4] = {av.x, av.y, av.z, av.w};
            float b_[4] = {bv.x, bv.y, bv.z, bv.w};
            #pragma unroll
            for (int i = 0; i < 4; i++)
                #pragma unroll
                for (int j = 0; j < 4; j++)
                    acc[i][j] += a_[i] * b_[j];
        }
        __syncthreads();
    }

    #pragma unroll
    for (int i = 0; i < 4; i++) {
        float4 v = make_float4(acc[i][0], acc[i][1], acc[i][2], acc[i][3]);
        *(float4*)&C[(row0 + ty * 4 + i) * NH + col0 + tx * 4] = v;
    }
}

// ---------------------------------------------------------------------------
// Fused attention, R1 mapping (warp = query, lane = key) with:
//  - 32-key double-buffered cp.async tiles (dynamic smem, 90KB, 2 blocks/SM)
//  - float4 accumulator (4 independent FFMA chains)
//  - batch-interleaved grid (b = blockIdx & 3)
// 256 blocks x 256 threads = 8 warps = 8 queries of batch b.
// ---------------------------------------------------------------------------
__global__ __launch_bounds__(256) void attn_kernel(
    const float* __restrict__ values,
    const float* __restrict__ wv,
    const int*   __restrict__ valid_lens,
    float*       __restrict__ out)
{
    extern __shared__ float smem[];
    float* kbuf   = &smem[OFF_KBUF];   // 2 x 32 x STRIDE
    float* attn_s = &smem[OFF_ATTN];   // 8 x NK
    float* s_qh   = &smem[OFF_QH];     // 8 x NH
    float* s_wv   = &smem[OFF_WV];     // NH

    const int t    = threadIdx.x;
    const int w    = t >> 5;           // warp = query-in-block
    const int lane = t & 31;
    const int b    = blockIdx.x & 3;   // batch-interleaved
    const int qblk = blockIdx.x >> 2;  // 0..63
    const int vl   = valid_lens[b];    // uniform across block

    const unsigned kbuf_u32 = (unsigned)__cvta_generic_to_shared(kbuf);

    // ---------------- prologue: stage qh + wv; prefetch kh tile 0 ----------
    const float* khb = &g_kh[(b * NK) * NH];
    {
        #pragma unroll
        for (int rr = 0; rr < 2; rr++) {
            int i = t + 256 * rr;              // 0..511 float4 slots (8 rows x 64)
            int r = i >> 6;
            int c = (i & 63) * 4;
            *(float4*)&s_qh[r * NH + c] =
                *(const float4*)&g_qh[(b * NQ + qblk * 8 + r) * NH + c];
        }
        if (t < 64) *(float4*)&s_wv[t * 4] = *(const float4*)&wv[t * 4];

        // prefetch kh tile 0: 32 keys x 256 h = 2048 float4, 8/thread
        #pragma unroll
        for (int r = 0; r < 8; ++r) {
            int i  = t + 256 * r;
            int k  = i >> 6;
            int h4 = (i & 63) * 4;
            cp16(kbuf_u32 + (unsigned)(k * STRIDE + h4) * 4u, khb + k * NH + h4);
        }
        cp_commit();
    }

    // ---------------- Phase A: scores -> attn_s ----------------
    const float* myq = &s_qh[w * NH];
    const int nTA = (vl + TK - 1) >> 5;

    for (int tile = 0; tile < nTA; ++tile) {
        if (tile + 1 < nTA) {                  // prefetch next into other buffer
            const float* src = &khb[(tile + 1) * TK * NH];
            unsigned dbase = kbuf_u32 + (unsigned)(((tile + 1) & 1) * TK * STRIDE) * 4u;
            #pragma unroll
            for (int r = 0; r < 8; ++r) {
                int i  = t + 256 * r;
                int k  = i >> 6;
                int h4 = (i & 63) * 4;
                cp16(dbase + (unsigned)(k * STRIDE + h4) * 4u, src + k * NH + h4);
            }
            cp_commit();
            asm volatile("cp.async.wait_group 1;");
        } else {
            asm volatile("cp.async.wait_group 0;");
        }
        __syncthreads();                       // tile data visible (also covers prologue)

        const float* myk = &kbuf[(tile & 1) * TK * STRIDE + lane * STRIDE];
        float4 a4 = make_float4(0.f, 0.f, 0.f, 0.f);
        #pragma unroll 8
        for (int h = 0; h < NH; h += 4) {
            float4 kv  = *(const float4*)&myk[h];
            float4 qv  = *(const float4*)&myq[h];    // broadcast
            float4 wv4 = *(const float4*)&s_wv[h];   // broadcast
            a4.x += wv4.x * tanh_ap(qv.x + kv.x);
            a4.y += wv4.y * tanh_ap(qv.y + kv.y);
            a4.z += wv4.z * tanh_ap(qv.z + kv.z);
            a4.w += wv4.w * tanh_ap(qv.w + kv.w);
        }
        attn_s[w * NK + tile * TK + lane] = (a4.x + a4.y) + (a4.z + a4.w);
        __syncthreads();                       // reads done before buffer reuse
    }

    // ---------------- prefetch values tile 0 (overlaps softmax) ------------
    const int nTC = (vl + TK - 1) >> 5;
    const float* vb = &values[(b * NK) * ND];
    {
        #pragma unroll
        for (int r = 0; r < 8; ++r) {
            int i  = t + 256 * r;
            int k  = i >> 6;
            int h4 = (i & 63) * 4;
            cp16(kbuf_u32 + (unsigned)(k * STRIDE + h4) * 4u, vb + k * ND + h4);
        }
        cp_commit();
    }

    // ---------------- Phase B: masked softmax (warp w = query w) -----------
    float mx = -1.0e30f;
    for (int i = 0; i < 16; i++) {
        int k = i * 32 + lane;
        float v = (k < vl) ? attn_s[w * NK + k] : -1.0e6f;
        mx = fmaxf(mx, v);
    }
    #pragma unroll
    for (int o = 16; o > 0; o >>= 1)
        mx = fmaxf(mx, __shfl_xor_sync(0xffffffffu, mx, o));

    float sum = 0.f;
    for (int i = 0; i < 16; i++) {
        int k = i * 32 + lane;
        float v = (k < vl) ? attn_s[w * NK + k] : -1.0e6f;
        float e = __expf(v - mx);              // masked -> exact 0
        sum += e;
        attn_s[w * NK + k] = e;                // unnormalized (warp-own row)
    }
    #pragma unroll
    for (int o = 16; o > 0; o >>= 1)
        sum += __shfl_xor_sync(0xffffffffu, sum, o);
    const float inv = 1.0f / sum;

    // ---------------- Phase C: out = attn @ values ----------------
    float4 o0 = make_float4(0.f, 0.f, 0.f, 0.f);
    float4 o1 = make_float4(0.f, 0.f, 0.f, 0.f);

    for (int tile = 0; tile < nTC; ++tile) {
        if (tile + 1 < nTC) {
            const float* src = &vb[(tile + 1) * TK * ND];
            unsigned dbase = kbuf_u32 + (unsigned)(((tile + 1) & 1) * TK * STRIDE) * 4u;
            #pragma unroll
            for (int r = 0; r < 8; ++r) {
                int i  = t + 256 * r;
                int k  = i >> 6;
                int h4 = (i & 63) * 4;
                cp16(dbase + (unsigned)(k * STRIDE + h4) * 4u, src + k * ND + h4);
            }
            cp_commit();
            asm volatile("cp.async.wait_group 1;");
        } else {
            asm volatile("cp.async.wait_group 0;");
        }
        __syncthreads();                       // tile data visible

        const float* vbuf = &kbuf[(tile & 1) * TK * STRIDE];
        #pragma unroll 8
        for (int kk = 0; kk < TK; ++kk) {
            float a = attn_s[w * NK + tile * TK + kk];   // broadcast (warp-own row)
            float4 v0 = *(const float4*)&vbuf[kk * STRIDE + 4 * lane];
            float4 v1 = *(const float4*)&vbuf[kk * STRIDE + 128 + 4 * lane];
            o0.x += a * v0.x; o0.y += a * v0.y; o0.z += a * v0.z; o0.w += a * v0.w;
            o1.x += a * v1.x; o1.y += a * v1.y; o1.z += a * v1.z; o1.w += a * v1.w;
        }
        __syncthreads();                       // reads done before buffer reuse
    }

    o0.x *= inv; o0.y *= inv; o0.z *= inv; o0.w *= inv;
    o1.x *= inv; o1.y *= inv; o1.z *= inv; o1.w *= inv;
    const int qrow = b * NQ + qblk * 8 + w;
    *(float4*)&out[qrow * ND + 4 * lane]       = o0;
    *(float4*)&out[qrow * ND + 128 + 4 * lane] = o1;
}

// ---------------------------------------------------------------------------
extern "C" void kernel_launch(void* const* d_in, const int* in_sizes, int n_in,
                              void* d_out, int out_size)
{
    const float* queries = (const float*)d_in[0];
    const float* keys    = (const float*)d_in[1];
    const float* values  = (const float*)d_in[2];
    const float* Wq      = (const float*)d_in[3];
    const float* Wk      = (const float*)d_in[4];
    const float* wv      = (const float*)d_in[5];
    const int*   vlen    = (const int*)d_in[6];
    float* out = (float*)d_out;

    (void)in_sizes; (void)n_in; (void)out_size;

    // Deterministic, idempotent; persists from the uncaptured correctness call.
    cudaFuncSetAttribute(attn_kernel,
                         cudaFuncAttributeMaxDynamicSharedMemorySize, SMEM_BYTES);

    dim3 pgrid(NH / 64, (NB * NQ) / 64, 2);
    proj_kernel<<<pgrid, 256>>>(queries, Wq, keys, Wk);

    attn_kernel<<<(NB * NQ) / 8, 256, SMEM_BYTES>>>(values, wv, vlen, out);
}